// round 1
// baseline (speedup 1.0000x reference)
#include <cuda_runtime.h>
#include <math_constants.h>

// Causal sliding-window min, W = 128, via van Herk / Gil-Werman.
// Segment size == window size == 128. Each warp owns 4 contiguous segments.
// out[i] = min(prefix_seg[i], suffix_seg[i-127]); i-127 is in the previous
// segment (or same segment start when i is a segment end — formula still holds).

#define WSZ     128              // window / segment length
#define NWARPS  8
#define BLOCK   (NWARPS * 32)    // 256 threads
#define SEGS    32               // output segments per CTA
#define TILE    (SEGS * WSZ)     // 4096 elements per CTA

__global__ __launch_bounds__(BLOCK)
void swmin128_kernel(const float* __restrict__ x,
                     float* __restrict__ out,
                     long long n)
{
    // suffix arrays for halo segment (slot 0) + SEGS tile segments
    __shared__ float suf[(SEGS + 1) * WSZ];

    const int lane = threadIdx.x & 31;
    const int wid  = threadIdx.x >> 5;
    const long long tile_start = (long long)blockIdx.x * TILE;

    const float INF = CUDART_INF_F;

    // ---------------- Phase 1: suffix-min per segment ----------------

    // Halo segment (s = 0): suffix only, computed by warp 0.
    if (wid == 0) {
        long long in_base = tile_start - WSZ + (long long)lane * 4;
        float4 v;
        if (in_base >= 0 && in_base + 3 < n) {
            v = __ldcs((const float4*)(x + in_base));
        } else {
            v = make_float4(INF, INF, INF, INF);
        }
        float s3 = v.w;
        float s2 = fminf(v.z, s3);
        float s1 = fminf(v.y, s2);
        float s0 = fminf(v.x, s1);
        float m = s0;
        #pragma unroll
        for (int d = 1; d < 32; d <<= 1)
            m = fminf(m, __shfl_down_sync(0xffffffffu, m, d));
        float c = __shfl_down_sync(0xffffffffu, m, 1);
        if (lane == 31) c = INF;
        *(float4*)&suf[lane * 4] =
            make_float4(fminf(s0, c), fminf(s1, c), fminf(s2, c), fminf(s3, c));
    }

    // Tile segments: each warp owns 4 contiguous segments. Keep raw values in
    // registers for the prefix phase.
    float4 vreg[4];

    #pragma unroll
    for (int k = 0; k < 4; k++) {
        const int s = 1 + wid * 4 + k;                 // 1..SEGS
        long long in_base = tile_start + (long long)(s - 1) * WSZ + lane * 4;
        float4 v;
        if (in_base + 3 < n) {
            v = __ldcs((const float4*)(x + in_base));
        } else {
            v = make_float4(INF, INF, INF, INF);
        }
        vreg[k] = v;

        float s3 = v.w;
        float s2 = fminf(v.z, s3);
        float s1 = fminf(v.y, s2);
        float s0 = fminf(v.x, s1);
        float m = s0;
        #pragma unroll
        for (int d = 1; d < 32; d <<= 1)
            m = fminf(m, __shfl_down_sync(0xffffffffu, m, d));
        float c = __shfl_down_sync(0xffffffffu, m, 1);
        if (lane == 31) c = INF;
        *(float4*)&suf[s * WSZ + lane * 4] =
            make_float4(fminf(s0, c), fminf(s1, c), fminf(s2, c), fminf(s3, c));
    }

    __syncthreads();

    // ---------------- Phase 2: prefix-min + combine ----------------

    #pragma unroll
    for (int k = 0; k < 4; k++) {
        const int s = 1 + wid * 4 + k;
        float4 v = vreg[k];

        float p0 = v.x;
        float p1 = fminf(v.y, p0);
        float p2 = fminf(v.z, p1);
        float p3 = fminf(v.w, p2);
        float m = p3;
        #pragma unroll
        for (int d = 1; d < 32; d <<= 1)
            m = fminf(m, __shfl_up_sync(0xffffffffu, m, d));
        float c = __shfl_up_sync(0xffffffffu, m, 1);
        if (lane == 0) c = INF;

        // smem index of this output position; window tail is 127 behind
        const int si = s * WSZ + lane * 4;
        float e0 = fminf(fminf(p0, c), suf[si - 127]);
        float e1 = fminf(fminf(p1, c), suf[si - 126]);
        float e2 = fminf(fminf(p2, c), suf[si - 125]);
        float e3 = fminf(fminf(p3, c), suf[si - 124]);

        long long ob = tile_start + (long long)(s - 1) * WSZ + lane * 4;
        if (ob + 3 < n) {
            __stcs((float4*)(out + ob), make_float4(e0, e1, e2, e3));
        } else if (ob < n) {
            if (ob + 0 < n) out[ob + 0] = e0;
            if (ob + 1 < n) out[ob + 1] = e1;
            if (ob + 2 < n) out[ob + 2] = e2;
            if (ob + 3 < n) out[ob + 3] = e3;
        }
    }
}

extern "C" void kernel_launch(void* const* d_in, const int* in_sizes, int n_in,
                              void* d_out, int out_size)
{
    const float* x = (const float*)d_in[0];
    float* out = (float*)d_out;
    long long n = (long long)in_sizes[0];
    long long grid = (n + TILE - 1) / TILE;  // 2048 for N = 8,388,608
    swmin128_kernel<<<(unsigned)grid, BLOCK>>>(x, out, n);
}

// round 2
// speedup vs baseline: 1.1830x; 1.1830x over previous
#include <cuda_runtime.h>
#include <math_constants.h>

// Causal sliding-window min, W = 128, van Herk / Gil-Werman with
// segment == window == 128.
//
// out[global i in segment g at local p] = min(pref_g[p], suf_{g-1}[p+1]),
// with suf[128] := +inf.
//
// Each warp owns SEGW contiguous segments: the suffix array of segment k-1
// stays in registers across the loop, so the combine needs only one
// shfl_down (lane l needs suf_prev[4l+4] = lane l+1's suf_prev[4l+4... reg s0]).
// The warp's first segment needs the suffix of the preceding segment (owned
// by the neighboring warp / CTA): each warp redundantly loads + suffix-scans
// that halo segment. No shared memory, no __syncthreads.
//
// Both warp-level scans (forward + backward over the 32 lane-mins) come from
// ONE 5-step shfl_xor butterfly that maintains F (fwd incl), B (bwd incl),
// A (group total) simultaneously.

#define WSZ     128
#define NWARPS  8
#define BLOCK   (NWARPS * 32)     // 256
#define SEGW    4                 // segments per warp
#define SEGS    (NWARPS * SEGW)   // 32 segments per CTA
#define TILE    (SEGS * WSZ)      // 4096 elements per CTA

__global__ __launch_bounds__(BLOCK)
void swmin128_kernel(const float* __restrict__ x,
                     float* __restrict__ out,
                     long long n)
{
    const int lane = threadIdx.x & 31;
    const int wid  = threadIdx.x >> 5;
    const float INF = CUDART_INF_F;

    const long long warp_seg0 =
        (long long)blockIdx.x * SEGS + (long long)wid * SEGW;  // first global segment

    // ---------- halo: suffix array of segment (warp_seg0 - 1) ----------
    float ps0, ps1, ps2, ps3;   // suf_prev[4l + 0..3], register-resident
    {
        long long base = (warp_seg0 - 1) * WSZ + (long long)lane * 4;
        float4 v;
        if (base >= 0 && base + 3 < n) {
            v = *(const float4*)(x + base);
        } else {
            v = make_float4(INF, INF, INF, INF);
        }
        float s3 = v.w;
        float s2 = fminf(v.z, s3);
        float s1 = fminf(v.y, s2);
        float s0 = fminf(v.x, s1);          // lane min

        float B = s0, A = s0;               // backward-only butterfly
        #pragma unroll
        for (int d = 1; d < 32; d <<= 1) {
            float Ap = __shfl_xor_sync(0xffffffffu, A, d);
            if (!(lane & d)) B = fminf(B, Ap);
            A = fminf(A, Ap);
        }
        float sc = __shfl_down_sync(0xffffffffu, B, 1);   // excl suffix carry
        if (lane == 31) sc = INF;
        ps0 = fminf(s0, sc);
        ps1 = fminf(s1, sc);
        ps2 = fminf(s2, sc);
        ps3 = fminf(s3, sc);
    }

    // ---------- main segments ----------
    #pragma unroll
    for (int k = 0; k < SEGW; k++) {
        long long base = (warp_seg0 + k) * WSZ + (long long)lane * 4;
        bool ok = (base + 3 < n);
        float4 v;
        if (ok) {
            v = *(const float4*)(x + base);
        } else {
            v = make_float4(INF, INF, INF, INF);
        }

        // local prefix + suffix chains (run in parallel, 3 deps each)
        float p0 = v.x;
        float p1 = fminf(v.y, p0);
        float p2 = fminf(v.z, p1);
        float p3 = fminf(v.w, p2);
        float s3 = v.w;
        float s2 = fminf(v.z, s3);
        float s1 = fminf(v.y, s2);
        float s0 = fminf(v.x, s1);          // lane min (== p3)

        // bidirectional butterfly scan over lane mins: F fwd incl, B bwd incl
        float F = s0, B = s0, A = s0;
        #pragma unroll
        for (int d = 1; d < 32; d <<= 1) {
            float Ap = __shfl_xor_sync(0xffffffffu, A, d);
            if (lane & d) F = fminf(F, Ap);
            else          B = fminf(B, Ap);
            A = fminf(A, Ap);
        }
        float pc = __shfl_up_sync(0xffffffffu, F, 1);     // excl prefix carry
        if (lane == 0) pc = INF;
        float sc = __shfl_down_sync(0xffffffffu, B, 1);   // excl suffix carry
        if (lane == 31) sc = INF;

        // full prefix values at this lane's 4 positions
        float q0 = fminf(p0, pc);
        float q1 = fminf(p1, pc);
        float q2 = fminf(p2, pc);
        float q3 = fminf(p3, pc);

        // suf_prev[p+1]: needs lane l+1's ps0 for the last element
        float nxt = __shfl_down_sync(0xffffffffu, ps0, 1);
        if (lane == 31) nxt = INF;          // suf_prev[128] = +inf

        float e0 = fminf(q0, ps1);
        float e1 = fminf(q1, ps2);
        float e2 = fminf(q2, ps3);
        float e3 = fminf(q3, nxt);

        if (ok) {
            __stcs((float4*)(out + base), make_float4(e0, e1, e2, e3));
        } else if (base < n) {
            if (base + 0 < n) out[base + 0] = e0;
            if (base + 1 < n) out[base + 1] = e1;
            if (base + 2 < n) out[base + 2] = e2;
        }

        // hand suffix of this segment to the next iteration
        ps0 = fminf(s0, sc);
        ps1 = fminf(s1, sc);
        ps2 = fminf(s2, sc);
        ps3 = fminf(s3, sc);
    }
}

extern "C" void kernel_launch(void* const* d_in, const int* in_sizes, int n_in,
                              void* d_out, int out_size)
{
    const float* x = (const float*)d_in[0];
    float* out = (float*)d_out;
    long long n = (long long)in_sizes[0];
    long long grid = (n + TILE - 1) / TILE;   // 2048 for N = 8,388,608
    swmin128_kernel<<<(unsigned)grid, BLOCK>>>(x, out, n);
}

// round 5
// speedup vs baseline: 1.4048x; 1.1875x over previous
#include <cuda_runtime.h>
#include <math_constants.h>

// Causal sliding-window min, W = 128 == segment size (van Herk / Gil-Werman).
// out[seg g, local p] = min(pref_g[p], suf_{g-1}[p+1]),  suf[128] := +inf.
//
// Warp-per-segment, 4 elems/lane, SEGW=8 contiguous segments per warp plus a
// redundantly-loaded halo segment (suffix only). Suffix handoff is fully
// register-resident: lane l needs suf_prev at 4l+1..4l+4 = {ps1,ps2,ps3,psc},
// where psc (= previous iteration's suffix carry sc) covers 4l+4 — no extra
// shfl. One 5-step shfl_xor butterfly yields both directional scans.

#define WSZ     128
#define NWARPS  8
#define BLOCK   (NWARPS * 32)     // 256
#define SEGW    8                 // segments per warp
#define SEGS    (NWARPS * SEGW)   // 64 segments per CTA
#define TILE    (SEGS * WSZ)      // 8192 elements per CTA

__global__ __launch_bounds__(BLOCK)
void swmin128_kernel(const float* __restrict__ x,
                     float* __restrict__ out,
                     int n)
{
    const int lane = threadIdx.x & 31;
    const int wid  = threadIdx.x >> 5;
    const float INF = CUDART_INF_F;

    const int warp_seg0 = blockIdx.x * SEGS + wid * SEGW;
    const int wbase = warp_seg0 * WSZ + lane * 4;   // this lane's first position

    // ---------------- front-batched loads (MLP = 9) ----------------
    float4 vh;
    {
        int base = wbase - WSZ;
        if (base >= 0 && base + 3 < n) {
            vh = *(const float4*)(x + base);
        } else {
            vh = make_float4(INF, INF, INF, INF);
        }
    }
    float4 vr[SEGW];
    #pragma unroll
    for (int k = 0; k < SEGW; k++) {
        int base = wbase + k * WSZ;
        if (base + 3 < n) {
            vr[k] = *(const float4*)(x + base);
        } else {
            vr[k].x = (base + 0 < n) ? x[base + 0] : INF;
            vr[k].y = (base + 1 < n) ? x[base + 1] : INF;
            vr[k].z = (base + 2 < n) ? x[base + 2] : INF;
            vr[k].w = (base + 3 < n) ? x[base + 3] : INF;
        }
    }

    // ---------------- halo: suffix handoff registers ----------------
    float ps1, ps2, ps3, psc;
    {
        float s2 = fminf(vh.z, vh.w);
        float s1 = fminf(vh.y, s2);
        float s0 = fminf(vh.x, s1);         // lane min
        float B = s0, A = s0;               // backward-only butterfly
        #pragma unroll
        for (int d = 1; d < 32; d <<= 1) {
            float Ap = __shfl_xor_sync(0xffffffffu, A, d);
            if (!(lane & d)) B = fminf(B, Ap);
            A = fminf(A, Ap);
        }
        float sc = __shfl_down_sync(0xffffffffu, B, 1);
        if (lane == 31) sc = INF;
        ps1 = fminf(s1, sc);
        ps2 = fminf(s2, sc);
        ps3 = fminf(vh.w, sc);
        psc = sc;
    }

    // ---------------- main segments ----------------
    #pragma unroll
    for (int k = 0; k < SEGW; k++) {
        const float4 v = vr[k];

        // local prefix + suffix chains (independent, 3 deps each)
        float p1 = fminf(v.y, v.x);
        float p2 = fminf(v.z, p1);
        float p3 = fminf(v.w, p2);
        float s2 = fminf(v.z, v.w);
        float s1 = fminf(v.y, s2);
        float s0 = fminf(v.x, s1);          // lane min (== p3)

        // bidirectional butterfly over the 32 lane-mins
        float F = s0, B = s0, A = s0;
        #pragma unroll
        for (int d = 1; d < 32; d <<= 1) {
            float Ap = __shfl_xor_sync(0xffffffffu, A, d);
            if (lane & d) F = fminf(F, Ap);
            else          B = fminf(B, Ap);
            A = fminf(A, Ap);
        }
        float pc = __shfl_up_sync(0xffffffffu, F, 1);    // excl prefix carry
        if (lane == 0) pc = INF;
        float sc = __shfl_down_sync(0xffffffffu, B, 1);  // excl suffix carry
        if (lane == 31) sc = INF;

        // combine: full prefix ∧ previous-segment suffix (register-resident)
        float e0 = fminf(fminf(v.x, pc), ps1);
        float e1 = fminf(fminf(p1,  pc), ps2);
        float e2 = fminf(fminf(p2,  pc), ps3);
        float e3 = fminf(fminf(p3,  pc), psc);

        int base = wbase + k * WSZ;
        if (base + 3 < n) {
            __stcs((float4*)(out + base), make_float4(e0, e1, e2, e3));
        } else if (base < n) {
            out[base] = e0;
            if (base + 1 < n) out[base + 1] = e1;
            if (base + 2 < n) out[base + 2] = e2;
        }

        // suffix handoff to next segment
        ps1 = fminf(s1, sc);
        ps2 = fminf(s2, sc);
        ps3 = fminf(v.w, sc);
        psc = sc;
    }
}

extern "C" void kernel_launch(void* const* d_in, const int* in_sizes, int n_in,
                              void* d_out, int out_size)
{
    const float* x = (const float*)d_in[0];
    float* out = (float*)d_out;
    int n = in_sizes[0];
    int grid = (n + TILE - 1) / TILE;   // 1024 for N = 8,388,608
    swmin128_kernel<<<grid, BLOCK>>>(x, out, n);
}